// round 15
// baseline (speedup 1.0000x reference)
#include <cuda_runtime.h>
#include <cuda_bf16.h>

#define S 8192
#define H 2048

#define U_BLOCKS   1024
#define WARM_BLOCKS 148
#define WARM_F4     12288   // float4s per warm block (192 KB); 148*192KB = 28.4 MB

// Zero-initialized at module load; norm_kernel resets g_u / g_sum each run.
// g_dummy is overwritten with the same deterministic values every run.
__device__ float g_u[H];      // must be 0 at entry
__device__ float g_sum;       // must be 0 at entry
__device__ float g_dummy[WARM_BLOCKS];

// ---------------------------------------------------------------------------
// Kernel 1: two block roles, one launch (concurrent on different SMs):
//  blocks [0,1024):  u[k] += sum_j w[j] * W_att[j*2H + H + k]
//     (byte-identical to the best-measured r8 u path: 8 k-tiles x 128
//      j-chunks of 16 rows, staged scalar loads, 1 atomicAdd/thread)
//  blocks [1024,1172): L2-warm the first 28 MB of enc via __ldcg while the
//     u blocks leave ~70% of DRAM bandwidth idle. One block per SM; all
//     1172 blocks co-resident in wave 1 (<=8 blocks/SM at 256 thr/32 reg).
// ---------------------------------------------------------------------------
#define U_JROWS 16
__global__ void __launch_bounds__(256) u_warm_kernel(const float* __restrict__ W_att,
                                                     const float* __restrict__ w,
                                                     const float* __restrict__ enc) {
    const int t = threadIdx.x;
    const int b = blockIdx.x;

    if (b < U_BLOCKS) {
        // ---- u path (r8) ----
        const int k  = (b & 7) * 256 + t;
        const int j0 = (b >> 3) * U_JROWS;
        const float* base = W_att + (size_t)j0 * (2 * H) + H + k;

        float v[U_JROWS];
#pragma unroll
        for (int jj = 0; jj < U_JROWS; jj++)
            v[jj] = base[(size_t)jj * (2 * H)];

        float wr[U_JROWS];
#pragma unroll
        for (int jj = 0; jj < U_JROWS; jj++)
            wr[jj] = __ldg(&w[j0 + jj]);

        float a0 = 0.f, a1 = 0.f, a2 = 0.f, a3 = 0.f;
#pragma unroll
        for (int jj = 0; jj < U_JROWS; jj += 4) {
            a0 += wr[jj + 0] * v[jj + 0];
            a1 += wr[jj + 1] * v[jj + 1];
            a2 += wr[jj + 2] * v[jj + 2];
            a3 += wr[jj + 3] * v[jj + 3];
        }
        atomicAdd(&g_u[k], (a0 + a1) + (a2 + a3));
    } else {
        // ---- warm path: stream 192 KB of enc into L2 ----
        const int wb = b - U_BLOCKS;
        const float4* src = reinterpret_cast<const float4*>(enc)
                          + (size_t)wb * WARM_F4;
        float acc = 0.0f;
        // 48 f4/thread in 6 batches of 8 staged loads
#pragma unroll
        for (int batch = 0; batch < 6; batch++) {
            float4 vv[8];
#pragma unroll
            for (int i = 0; i < 8; i++)
                vv[i] = __ldcg(&src[(size_t)(batch * 8 + i) * 256 + t]);
#pragma unroll
            for (int i = 0; i < 8; i++)
                acc += vv[i].x + vv[i].y + vv[i].z + vv[i].w;
        }
        // one deterministic dummy store per warm block (same value each run)
        if (t == 0) { }
        float r = acc;
#pragma unroll
        for (int off = 16; off > 0; off >>= 1)
            r += __shfl_down_sync(0xffffffffu, r, off);
        __shared__ float sm[8];
        const int lane = t & 31, wid = t >> 5;
        if (lane == 0) sm[wid] = r;
        __syncthreads();
        if (t == 0) {
            float p = 0.0f;
#pragma unroll
            for (int w8 = 0; w8 < 8; w8++) p += sm[w8];
            g_dummy[wb] = p;
        }
    }
}

// ---------------------------------------------------------------------------
// Kernel 2 (fused score+exp): e[s] = exp(dot(enc[s], u)), 8 rows/block,
// one atomicAdd of the block partial sum. No max subtraction (scores
// ~N(0,18.5^2); max over 8192 ~ 70 << 88 -> exp finite; tiny terms underflow
// identically with or without the shift).
// (byte-identical to the 18.9us round-8 version)
// ---------------------------------------------------------------------------
#define ROWS_PER_BLK 8
__global__ void __launch_bounds__(256) score_kernel(const float* __restrict__ enc,
                                                    float* __restrict__ out) {
    const int t    = threadIdx.x;
    const int row0 = blockIdx.x * ROWS_PER_BLK;

    const float4* up = reinterpret_cast<const float4*>(g_u) + t * 2;
    const float4 u0 = up[0], u1 = up[1];

    float acc[ROWS_PER_BLK];
#pragma unroll
    for (int r = 0; r < ROWS_PER_BLK; r++) {
        const float4* e = reinterpret_cast<const float4*>(
                              enc + (size_t)(row0 + r) * H) + t * 2;
        const float4 e0 = e[0], e1 = e[1];
        acc[r] = e0.x * u0.x + e0.y * u0.y + e0.z * u0.z + e0.w * u0.w
               + e1.x * u1.x + e1.y * u1.y + e1.z * u1.z + e1.w * u1.w;
    }

    __shared__ float sm[8][ROWS_PER_BLK];
    const int lane = t & 31, wid = t >> 5;
#pragma unroll
    for (int r = 0; r < ROWS_PER_BLK; r++) {
        float v = acc[r];
#pragma unroll
        for (int off = 16; off > 0; off >>= 1)
            v += __shfl_down_sync(0xffffffffu, v, off);
        if (lane == 0) sm[wid][r] = v;
    }
    __syncthreads();

    if (wid == 0) {
        float e = 0.0f;
        if (lane < ROWS_PER_BLK) {
            float v = 0.0f;
#pragma unroll
            for (int w8 = 0; w8 < 8; w8++) v += sm[w8][lane];
            e = expf(v);
            out[row0 + lane] = e;
        }
#pragma unroll
        for (int off = 4; off > 0; off >>= 1)
            e += __shfl_down_sync(0xffffffffu, e, off);
        if (lane == 0) atomicAdd(&g_sum, e);
    }
}

// ---------------------------------------------------------------------------
// Kernel 3: normalize out in place; resets persistent state for next replay.
// (byte-identical to round-8)
// ---------------------------------------------------------------------------
__global__ void __launch_bounds__(1024) norm_kernel(float* __restrict__ out) {
    const int t = threadIdx.x;
    __shared__ float s_inv;
    if (t == 0) s_inv = 1.0f / g_sum;
    __syncthreads();
    const float inv = s_inv;
    const int s = blockIdx.x * 1024 + t;
    out[s] *= inv;

    // state reset for next replay
    if (blockIdx.x < 2) g_u[blockIdx.x * 1024 + t] = 0.0f;
    if (blockIdx.x == 2 && t == 0) g_sum = 0.0f;
}

// ---------------------------------------------------------------------------
// Inputs (metadata order): encoder_outputs (S*1*H), hidden (H),
//                          W_att (H*2H), b_att (H), w (1*H)
// hidden / b_att / left half of W_att drop out (softmax shift invariance).
// ---------------------------------------------------------------------------
extern "C" void kernel_launch(void* const* d_in, const int* in_sizes, int n_in,
                              void* d_out, int out_size) {
    const float* enc   = (const float*)d_in[0];
    const float* W_att = (const float*)d_in[2];
    const float* w     = (const float*)d_in[4];
    float* out = (float*)d_out;

    u_warm_kernel<<<U_BLOCKS + WARM_BLOCKS, 256>>>(W_att, w, enc);
    score_kernel<<<S / ROWS_PER_BLK, 256>>>(enc, out);
    norm_kernel<<<8, 1024>>>(out);
}